// round 10
// baseline (speedup 1.0000x reference)
#include <cuda_runtime.h>
#include <cstdint>

typedef uint32_t u32;

__device__ __forceinline__ u32 pkbf(float lo, float hi) {
    u32 r; asm("cvt.rn.bf16x2.f32 %0, %1, %2;" : "=r"(r) : "f"(hi), "f"(lo)); return r;
}
__device__ __forceinline__ float bflo(u32 h) { return __uint_as_float(h << 16); }
__device__ __forceinline__ float bfhi(u32 h) { return __uint_as_float(h & 0xFFFF0000u); }
__device__ __forceinline__ void split2(float a, float b, u32& hp, u32& lp) {
    hp = pkbf(a, b);
    lp = pkbf(a - bflo(hp), b - bfhi(hp));
}

#define MMA(d, a0, a1, a2, a3, b0, b1)                                      \
    asm volatile("mma.sync.aligned.m16n8k16.row.col.f32.bf16.bf16.f32 "     \
                 "{%0,%1,%2,%3},{%4,%5,%6,%7},{%8,%9},{%0,%1,%2,%3};"       \
                 : "+f"((d)[0]), "+f"((d)[1]), "+f"((d)[2]), "+f"((d)[3])   \
                 : "r"(a0), "r"(a1), "r"(a2), "r"(a3), "r"(b0), "r"(b1))

// bias + LN + leaky on [16 x 32] block; emit next-stage A frags
__device__ __forceinline__ void ln_block(float acc[4][4],
                                         const float* __restrict__ bias,
                                         const float* __restrict__ gg,
                                         const float* __restrict__ bb,
                                         int t, u32 oh[2][4], u32 ol[2][4])
{
    float s0 = 0.f, q0 = 0.f, s1 = 0.f, q1 = 0.f;
#pragma unroll
    for (int nn = 0; nn < 4; nn++) {
        float2 bv = *(const float2*)(bias + 8 * nn + 2 * t);
        acc[nn][0] += bv.x; acc[nn][1] += bv.y;
        acc[nn][2] += bv.x; acc[nn][3] += bv.y;
        s0 += acc[nn][0] + acc[nn][1];
        q0 += acc[nn][0] * acc[nn][0] + acc[nn][1] * acc[nn][1];
        s1 += acc[nn][2] + acc[nn][3];
        q1 += acc[nn][2] * acc[nn][2] + acc[nn][3] * acc[nn][3];
    }
#pragma unroll
    for (int m = 1; m < 4; m <<= 1) {
        s0 += __shfl_xor_sync(0xffffffffu, s0, m, 4);
        q0 += __shfl_xor_sync(0xffffffffu, q0, m, 4);
        s1 += __shfl_xor_sync(0xffffffffu, s1, m, 4);
        q1 += __shfl_xor_sync(0xffffffffu, q1, m, 4);
    }
    const float c = 1.0f / 32.0f;
    const float m0 = s0 * c, r0 = rsqrtf(fmaf(-m0, m0, q0 * c) + 1e-5f);
    const float m1 = s1 * c, r1 = rsqrtf(fmaf(-m1, m1, q1 * c) + 1e-5f);

    float y[4][4];
#pragma unroll
    for (int nn = 0; nn < 4; nn++) {
        float2 gv = *(const float2*)(gg + 8 * nn + 2 * t);
        float2 bv = *(const float2*)(bb + 8 * nn + 2 * t);
        float u;
        u = fmaf((acc[nn][0] - m0) * r0, gv.x, bv.x); y[nn][0] = fmaxf(u, 0.01f * u);
        u = fmaf((acc[nn][1] - m0) * r0, gv.y, bv.y); y[nn][1] = fmaxf(u, 0.01f * u);
        u = fmaf((acc[nn][2] - m1) * r1, gv.x, bv.x); y[nn][2] = fmaxf(u, 0.01f * u);
        u = fmaf((acc[nn][3] - m1) * r1, gv.y, bv.y); y[nn][3] = fmaxf(u, 0.01f * u);
    }
#pragma unroll
    for (int kk = 0; kk < 2; kk++) {
        split2(y[2 * kk][0],     y[2 * kk][1],     oh[kk][0], ol[kk][0]);
        split2(y[2 * kk][2],     y[2 * kk][3],     oh[kk][1], ol[kk][1]);
        split2(y[2 * kk + 1][0], y[2 * kk + 1][1], oh[kk][2], ol[kk][2]);
        split2(y[2 * kk + 1][2], y[2 * kk + 1][3], oh[kk][3], ol[kk][3]);
    }
}

// load x for one tile; also L2-prefetch tile at +pfoff floats (next+stride)
__device__ __forceinline__ void loadx(const float* __restrict__ x, int tile, int g, int t,
                                      int nrows, float4 xa[4], float4 xb[4],
                                      size_t pfoff, bool dopf)
{
    const int r0 = tile * 16 + g, r1 = r0 + 8;
    const float* b0 = x + (size_t)r0 * 64 + 4 * t;
    const float* b1 = x + (size_t)r1 * 64 + 4 * t;
    const bool v0 = r0 < nrows, v1 = r1 < nrows;
#pragma unroll
    for (int kk = 0; kk < 4; kk++) {
        xa[kk] = v0 ? __ldcs((const float4*)(b0 + 16 * kk)) : make_float4(0.f, 0.f, 0.f, 0.f);
        xb[kk] = v1 ? __ldcs((const float4*)(b1 + 16 * kk)) : make_float4(0.f, 0.f, 0.f, 0.f);
    }
    if (dopf) {
        asm volatile("prefetch.global.L2 [%0];" :: "l"(b0 + pfoff));
        asm volatile("prefetch.global.L2 [%0];" :: "l"(b0 + pfoff + 32));
        asm volatile("prefetch.global.L2 [%0];" :: "l"(b1 + pfoff));
        asm volatile("prefetch.global.L2 [%0];" :: "l"(b1 + pfoff + 32));
    }
}

// ---------------- single fused kernel: per-CTA weight fold + persistent loop ----------------
__global__ void __launch_bounds__(128, 4)
fused_kernel(const float* __restrict__ x, float* __restrict__ out,
             const float* __restrict__ w1,  const float* __restrict__ b1,
             const float* __restrict__ wv1, const float* __restrict__ bv1,
             const float* __restrict__ g1,
             const float* __restrict__ l1g, const float* __restrict__ l1b,
             const float* __restrict__ w2,  const float* __restrict__ b2,
             const float* __restrict__ wv2, const float* __restrict__ bv2,
             const float* __restrict__ g2,
             const float* __restrict__ l2g, const float* __restrict__ l2b,
             const float* __restrict__ wo,  const float* __restrict__ bo,
             int nrows, int ntiles)
{
    __shared__ uint4 w1s[512];            // GEMM1 frags (8 KB)
    __shared__ uint4 w2s[256];            // GEMM2 frags (4 KB)
    __shared__ uint4 w3s[512];            // GEMM3 frags (8 KB)
    __shared__ float sp[192];             // ab | l1g | l1b | cb | l2g | l2b
    __shared__ float bos[64];
    __shared__ float scr[2048];           // fold scratch: Af (8 KB), then Cf (4 KB)
    const int tid = threadIdx.x;
    const float g1v = g1[0], g2v = g2[0];

    // ---- per-CTA weight fold + frag packing (replaces separate prep launch) ----
    // Af = w1 @ (I + g1*wv1)  -> scr[0..2047]
    for (int idx = tid; idx < 64 * 32; idx += 128) {
        int i = idx >> 5, j = idx & 31;
        float s = 0.f;
        for (int m = 0; m < 32; m++) s += w1[i * 32 + m] * wv1[m * 32 + j];
        scr[idx] = w1[i * 32 + j] + g1v * s;
    }
    __syncthreads();
    // pack w1 frags (K-permuted for coalesced x loads)
    for (int idx = tid; idx < 512; idx += 128) {
        int kk = idx >> 7, nn = (idx >> 5) & 3, ln = idx & 31;
        int gg = ln >> 2, tt = ln & 3;
        int kb = 16 * kk + 4 * tt, n = 8 * nn + gg;
        float a0 = scr[kb * 32 + n],       a1 = scr[(kb + 1) * 32 + n];
        float a2 = scr[(kb + 2) * 32 + n], a3 = scr[(kb + 3) * 32 + n];
        uint4 v;
        v.x = pkbf(a0, a1); v.y = pkbf(a2, a3);
        v.z = pkbf(a0 - bflo(v.x), a1 - bfhi(v.x));
        v.w = pkbf(a2 - bflo(v.y), a3 - bfhi(v.y));
        w1s[(kk * 4 + nn) * 32 + ln] = v;
    }
    __syncthreads();
    // Cf = w2 @ (I + g2*wv2) -> scr[0..1023]
    for (int idx = tid; idx < 32 * 32; idx += 128) {
        int i = idx >> 5, j = idx & 31;
        float s = 0.f;
        for (int m = 0; m < 32; m++) s += w2[i * 32 + m] * wv2[m * 32 + j];
        scr[idx] = w2[i * 32 + j] + g2v * s;
    }
    __syncthreads();
    // pack w2 frags (identity layout)
    for (int idx = tid; idx < 256; idx += 128) {
        int kk = idx >> 7, nn = (idx >> 5) & 3, ln = idx & 31;
        int gg = ln >> 2, tt = ln & 3;
        int k0 = 16 * kk + 2 * tt, n = 8 * nn + gg;
        float a0 = scr[k0 * 32 + n],       a1 = scr[(k0 + 1) * 32 + n];
        float a2 = scr[(k0 + 8) * 32 + n], a3 = scr[(k0 + 9) * 32 + n];
        uint4 v;
        v.x = pkbf(a0, a1); v.y = pkbf(a2, a3);
        v.z = pkbf(a0 - bflo(v.x), a1 - bfhi(v.x));
        v.w = pkbf(a2 - bflo(v.y), a3 - bfhi(v.y));
        w2s[(kk * 4 + nn) * 32 + ln] = v;
    }
    // pack w3 frags from global wo (no fold), output-column permuted
    for (int idx = tid; idx < 512; idx += 128) {
        int kk = idx >> 8, nn = (idx >> 5) & 7, ln = idx & 31;
        int gg = ln >> 2, tt = ln & 3;
        int k0 = 16 * kk + 2 * tt;
        int c = 16 * (nn >> 1) + 4 * (gg >> 1) + 2 * (nn & 1) + (gg & 1);
        float a0 = wo[k0 * 64 + c],       a1 = wo[(k0 + 1) * 64 + c];
        float a2 = wo[(k0 + 8) * 64 + c], a3 = wo[(k0 + 9) * 64 + c];
        uint4 v;
        v.x = pkbf(a0, a1); v.y = pkbf(a2, a3);
        v.z = pkbf(a0 - bflo(v.x), a1 - bfhi(v.x));
        v.w = pkbf(a2 - bflo(v.y), a3 - bfhi(v.y));
        w3s[(kk * 8 + nn) * 32 + ln] = v;
    }
    // folded biases + LN params
    if (tid < 32) {
        int j = tid;
        float s1 = 0.f, s2 = 0.f;
        for (int m = 0; m < 32; m++) {
            s1 += b1[m] * wv1[m * 32 + j];
            s2 += b2[m] * wv2[m * 32 + j];
        }
        sp[j]       = b1[j] + g1v * (s1 + bv1[j]);
        sp[96 + j]  = b2[j] + g2v * (s2 + bv2[j]);
        sp[32 + j]  = l1g[j];
        sp[64 + j]  = l1b[j];
        sp[128 + j] = l2g[j];
        sp[160 + j] = l2b[j];
    }
    if (tid < 64) bos[tid] = bo[tid];
    __syncthreads();

    const int wid = tid >> 5, lane = tid & 31;
    const int g = lane >> 2, t = lane & 3;

    const int stride = gridDim.x * 4;
    const size_t pfoff = (size_t)stride * 16 * 64;   // one more stride, in floats
    int tile = blockIdx.x * 4 + wid;
    if (tile >= ntiles) return;

    float4 xa[4], xb[4];
    loadx(x, tile, g, t, nrows, xa, xb, pfoff, tile + 2 * stride < ntiles);

    for (; tile < ntiles; tile += stride) {
        // ---- convert current x to hi/lo A frags ----
        u32 ah[4][4], al[4][4];
#pragma unroll
        for (int kk = 0; kk < 4; kk++) {
            split2(xa[kk].x, xa[kk].y, ah[kk][0], al[kk][0]);
            split2(xb[kk].x, xb[kk].y, ah[kk][1], al[kk][1]);
            split2(xa[kk].z, xa[kk].w, ah[kk][2], al[kk][2]);
            split2(xb[kk].z, xb[kk].w, ah[kk][3], al[kk][3]);
        }
        if (tile + stride < ntiles)
            loadx(x, tile + stride, g, t, nrows, xa, xb, pfoff, tile + 3 * stride < ntiles);

        // ---- GEMM1: [16x64]@[64x32] ----
        float acc[4][4];
#pragma unroll
        for (int nn = 0; nn < 4; nn++) {
            acc[nn][0] = acc[nn][1] = acc[nn][2] = acc[nn][3] = 0.f;
#pragma unroll
            for (int kk = 0; kk < 4; kk++) {
                uint4 w = w1s[(kk * 4 + nn) * 32 + lane];
                MMA(acc[nn], ah[kk][0], ah[kk][1], ah[kk][2], ah[kk][3], w.x, w.y);
                MMA(acc[nn], al[kk][0], al[kk][1], al[kk][2], al[kk][3], w.x, w.y);
                MMA(acc[nn], ah[kk][0], ah[kk][1], ah[kk][2], ah[kk][3], w.z, w.w);
            }
        }

        u32 a2h[2][4], a2l[2][4];
        ln_block(acc, sp + 0, sp + 32, sp + 64, t, a2h, a2l);

        // ---- GEMM2: [16x32]@[32x32] ----
        float acc2[4][4];
#pragma unroll
        for (int nn = 0; nn < 4; nn++) {
            acc2[nn][0] = acc2[nn][1] = acc2[nn][2] = acc2[nn][3] = 0.f;
#pragma unroll
            for (int kk = 0; kk < 2; kk++) {
                uint4 w = w2s[(kk * 4 + nn) * 32 + lane];
                MMA(acc2[nn], a2h[kk][0], a2h[kk][1], a2h[kk][2], a2h[kk][3], w.x, w.y);
                MMA(acc2[nn], a2l[kk][0], a2l[kk][1], a2l[kk][2], a2l[kk][3], w.x, w.y);
                MMA(acc2[nn], a2h[kk][0], a2h[kk][1], a2h[kk][2], a2h[kk][3], w.z, w.w);
            }
        }

        u32 a3h[2][4], a3l[2][4];
        ln_block(acc2, sp + 96, sp + 128, sp + 160, t, a3h, a3l);

        // ---- GEMM3: [16x32]@[32x64], store-permuted cols ----
        float acc3[8][4];
#pragma unroll
        for (int nn = 0; nn < 8; nn++) {
            acc3[nn][0] = acc3[nn][1] = acc3[nn][2] = acc3[nn][3] = 0.f;
#pragma unroll
            for (int kk = 0; kk < 2; kk++) {
                uint4 w = w3s[(kk * 8 + nn) * 32 + lane];
                MMA(acc3[nn], a3h[kk][0], a3h[kk][1], a3h[kk][2], a3h[kk][3], w.x, w.y);
                MMA(acc3[nn], a3l[kk][0], a3l[kk][1], a3l[kk][2], a3l[kk][3], w.x, w.y);
                MMA(acc3[nn], a3h[kk][0], a3h[kk][1], a3h[kk][2], a3h[kk][3], w.z, w.w);
            }
        }

        // ---- + bo, coalesced stores: instr j writes float4 @ logical col 16j+4t ----
        const int r0 = tile * 16 + g, r1 = r0 + 8;
        float* o0 = out + (size_t)r0 * 64;
        float* o1 = out + (size_t)r1 * 64;
        const bool v0 = r0 < nrows, v1 = r1 < nrows;
#pragma unroll
        for (int j = 0; j < 4; j++) {
            float4 b = *(const float4*)(bos + 16 * j + 4 * t);
            if (v0) {
                float4 v;
                v.x = acc3[2 * j][0]     + b.x;
                v.y = acc3[2 * j][1]     + b.y;
                v.z = acc3[2 * j + 1][0] + b.z;
                v.w = acc3[2 * j + 1][1] + b.w;
                __stcs((float4*)(o0 + 16 * j + 4 * t), v);
            }
            if (v1) {
                float4 v;
                v.x = acc3[2 * j][2]     + b.x;
                v.y = acc3[2 * j][3]     + b.y;
                v.z = acc3[2 * j + 1][2] + b.z;
                v.w = acc3[2 * j + 1][3] + b.w;
                __stcs((float4*)(o1 + 16 * j + 4 * t), v);
            }
        }
    }
}

extern "C" void kernel_launch(void* const* d_in, const int* in_sizes, int n_in,
                              void* d_out, int out_size)
{
    const float* x   = (const float*)d_in[0];
    const float* w1  = (const float*)d_in[1];
    const float* b1  = (const float*)d_in[2];
    const float* wv1 = (const float*)d_in[7];
    const float* bv1 = (const float*)d_in[8];
    const float* g1  = (const float*)d_in[9];
    const float* l1g = (const float*)d_in[10];
    const float* l1b = (const float*)d_in[11];
    const float* w2  = (const float*)d_in[12];
    const float* b2  = (const float*)d_in[13];
    const float* wv2 = (const float*)d_in[18];
    const float* bv2 = (const float*)d_in[19];
    const float* g2  = (const float*)d_in[20];
    const float* l2g = (const float*)d_in[21];
    const float* l2b = (const float*)d_in[22];
    const float* wo  = (const float*)d_in[23];
    const float* bo  = (const float*)d_in[24];

    const int B = in_sizes[0] / 64;
    const int ntiles = (B + 15) / 16;

    int grid = 4 * 148;                       // 4 CTAs/SM x 4 warps, persistent, one launch
    int need = (ntiles + 3) / 4;
    if (grid > need) grid = need;
    fused_kernel<<<grid, 128>>>(x, (float*)d_out,
                                w1, b1, wv1, bv1, g1, l1g, l1b,
                                w2, b2, wv2, bv2, g2, l2g, l2b, wo, bo,
                                B, ntiles);
}